// round 4
// baseline (speedup 1.0000x reference)
#include <cuda_runtime.h>
#include <math.h>

#define LDIM 32
#define HDIM 64

typedef unsigned long long ull;

__device__ __forceinline__ ull pack2(float lo, float hi) {
    ull r; asm("mov.b64 %0, {%1, %2};" : "=l"(r) : "f"(lo), "f"(hi)); return r;
}
__device__ __forceinline__ float2 unpack2(ull v) {
    float2 r; asm("mov.b64 {%0, %1}, %2;" : "=f"(r.x), "=f"(r.y) : "l"(v)); return r;
}
#define FMA2(d, a, b, c) \
    asm("fma.rn.f32x2 %0, %1, %2, %3;" : "=l"(d) : "l"(a), "l"(b), "l"(c))

// One sample per block of 64 threads (2 warps); thread owns ONE channel ch.
// Wc column ch lives in registers as 32 packed f32x2 pairs.
// u = h + carry-from-above broadcast via double-buffered smem; one
// __syncthreads per step. Log-softmax is a 2-stage deferred pipeline:
//   step j   : pz kept in registers
//   step j+1 : warp shfl-reduce pz, lane0 stages per-warp sums to smem
//   step j+2 : all threads uniformly compute the lse and accumulate
// so no reduction chain ever gates the per-step barrier.
__global__ void __launch_bounds__(64) rnn2d_kernel(
    const int*   __restrict__ x,     // (B, 32, 32) int32, values in {0,1}
    const float* __restrict__ Win,   // (2, 64)
    const float* __restrict__ Wc,    // (64, 64)
    const float* __restrict__ bc,    // (64,)
    const float* __restrict__ Wout,  // (64, 2)
    const float* __restrict__ bout,  // (2,)
    float*       __restrict__ out)   // (B,)
{
    const int b    = blockIdx.x;
    const int ch   = threadIdx.x;    // 0..63 — owned output channel
    const int lane = ch & 31;
    const int w    = ch >> 5;

    __shared__ float Hprev[LDIM][HDIM];          // [col][ch] — thread-private entries
    __shared__ float ubuf[2][HDIM];              // double-buffered u (k-order)
    __shared__ int   xrow[2][LDIM];
    __shared__ __align__(16) float zpart[2][4];  // [p][z0w0,z1w0,z0w1,z1w1]

    // ---- weights ----
    ull wcp[HDIM / 2];
#pragma unroll
    for (int k = 0; k < HDIM / 2; ++k)
        wcp[k] = pack2(Wc[(2 * k) * HDIM + ch], Wc[(2 * k + 1) * HDIM + ch]);
    const float win0 = Win[ch], win1 = Win[HDIM + ch];
    const float bcr  = bc[ch];
    const float wo0  = Wout[ch * 2], wo1 = Wout[ch * 2 + 1];
    const float bo0  = bout[0],      bo1 = bout[1];

#pragma unroll
    for (int c = 0; c < LDIM; ++c) Hprev[c][ch] = 0.0f;
    if (ch < 8) ((float*)zpart)[ch] = 0.0f;      // finite garbage for warm-up lse

    const int* xb = x + b * LDIM * LDIM;

    float logp = 0.0f;
    float ppz0 = 0.0f, ppz1 = 0.0f;   // stage-1 pending (regs, step j-1)
    int   pxC1 = 0,    pxC2 = 0;      // x at steps j-1 / j-2
    float pend1 = 0.0f, pend2 = 0.0f; // validity scales
    float hp = 0.0f;                  // prefetched carry-from-above

    for (int i = 0; i < LDIM; ++i) {
        __syncthreads();                          // row i-1 fully done with xrow[i&1]
        if (ch < LDIM) xrow[i & 1][ch] = xb[i * LDIM + ch];

        const int dir  = (i & 1) ? -1 : 1;
        const int cur  = i & 1;
        const int prev = cur ^ 1;

        float h = 0.0f;
        int   xL = 0;

#pragma unroll 2
        for (int jj = 0; jj < LDIM; ++jj) {
            const int c = (i & 1) ? (LDIM - 1 - jj) : jj;
            const int p = jj & 1;

            // ---- pre-barrier: write u, compute r (reads only stable state) ----
            const float u = h + hp;
            ubuf[p][ch] = u;

            float r = bcr;
            if (jj > 0) r += xL ? win1 : win0;
            if (i  > 0) r += xrow[prev][c] ? win1 : win0;

            __syncthreads();

            // ---- stage 2: shfl-reduce step j-1's partials, stage to smem ----
            float rz0 = ppz0, rz1 = ppz1;
#pragma unroll
            for (int off = 16; off > 0; off >>= 1) {
                rz0 += __shfl_xor_sync(0xffffffffu, rz0, off);
                rz1 += __shfl_xor_sync(0xffffffffu, rz1, off);
            }
            if (lane == 0) {
                zpart[p ^ 1][w * 2]     = rz0;
                zpart[p ^ 1][w * 2 + 1] = rz1;
            }

            // ---- stage 3: lse of step j-2 (uniform, no divergence) ----
            {
                const float4 zp = *(const float4*)&zpart[p][0];
                const float z0 = zp.x + zp.z + bo0;
                const float z1 = zp.y + zp.w + bo1;
                const float m   = fmaxf(z0, z1);
                const float lse = m + __logf(__expf(z0 - m) + __expf(z1 - m));
                float lp = (pxC2 ? z1 : z0) - lse;
                if (lp != lp) lp = -35.0f;
                logp += pend2 * lp;
            }

            // ---- matvec: 16 packed f32x2 FMAs over register Wc column ----
            ull a0 = pack2(r, 0.0f), a1 = 0;
            const ulonglong2* up = (const ulonglong2*)ubuf[p];
#pragma unroll
            for (int k = 0; k < HDIM / 4; ++k) {
                const ulonglong2 uv = up[k];
                FMA2(a0, uv.x, wcp[2 * k],     a0);
                FMA2(a1, uv.y, wcp[2 * k + 1], a1);
            }
            const float2 f0 = unpack2(a0), f1 = unpack2(a1);
            const float  s  = (f0.x + f0.y) + (f1.x + f1.y);

            // elu (alpha = 1), fast-math exp
            const float nh = (s > 0.0f) ? s : (__expf(s) - 1.0f);

            // ---- stage 1: stash this step's logit partials in registers ----
            pend2 = pend1;  pxC2 = pxC1;
            ppz0 = nh * wo0;
            ppz1 = nh * wo1;
            pxC1 = xrow[cur][c];
            pend1 = 1.0f;

            // writeback + prefetch next carry-from-above (thread-private)
            Hprev[c][ch] = nh;
            const int cn = (jj < LDIM - 1) ? (c + dir) : c;
            hp = Hprev[cn][ch];
            h  = nh;

            xL = pxC1;
        }
    }

    // ---- flush the 2-step pipeline tail ----
    // After the loop: zpart[0] holds step 1022 (parity 0); step 1023's pz is
    // still in registers (parity 1).
    __syncthreads();
    {
        const float4 zp = *(const float4*)&zpart[0][0];
        const float z0 = zp.x + zp.z + bo0;
        const float z1 = zp.y + zp.w + bo1;
        const float m   = fmaxf(z0, z1);
        const float lse = m + __logf(__expf(z0 - m) + __expf(z1 - m));
        float lp = (pxC2 ? z1 : z0) - lse;
        if (lp != lp) lp = -35.0f;
        logp += pend2 * lp;
    }
    {
        float rz0 = ppz0, rz1 = ppz1;
#pragma unroll
        for (int off = 16; off > 0; off >>= 1) {
            rz0 += __shfl_xor_sync(0xffffffffu, rz0, off);
            rz1 += __shfl_xor_sync(0xffffffffu, rz1, off);
        }
        if (lane == 0) {
            zpart[1][w * 2]     = rz0;
            zpart[1][w * 2 + 1] = rz1;
        }
    }
    __syncthreads();
    {
        const float4 zp = *(const float4*)&zpart[1][0];
        const float z0 = zp.x + zp.z + bo0;
        const float z1 = zp.y + zp.w + bo1;
        const float m   = fmaxf(z0, z1);
        const float lse = m + __logf(__expf(z0 - m) + __expf(z1 - m));
        float lp = (pxC1 ? z1 : z0) - lse;
        if (lp != lp) lp = -35.0f;
        logp += pend1 * lp;
    }

    if (ch == 0) out[b] = 0.5f * logp;
}

extern "C" void kernel_launch(void* const* d_in, const int* in_sizes, int n_in,
                              void* d_out, int out_size) {
    const int*   x    = (const int*)  d_in[0];
    const float* Win  = (const float*)d_in[1];
    const float* Wc   = (const float*)d_in[2];
    const float* bc   = (const float*)d_in[3];
    const float* Wout = (const float*)d_in[4];
    const float* bout = (const float*)d_in[5];
    float* out = (float*)d_out;

    const int B = in_sizes[0] / (LDIM * LDIM);
    rnn2d_kernel<<<B, 64>>>(x, Win, Wc, bc, Wout, bout, out);
}